// round 2
// baseline (speedup 1.0000x reference)
#include <cuda_runtime.h>
#include <cstdint>

// ---------------------------------------------------------------------------
// KeyedGRU  (B=64, T=2048, I=H=256, KB=4, KL=16)
// inputs: x[64,2048,256], wm_key[4,16,256], weight_ih[768,256],
//         weight_hh[768,256], bias_ih[768], bias_hh[768]  (all f32)
// output: out[2048,64,256] f32
//
// A: gi GEMM for all (t,b) rows + key rows -> g_gi  (parallel)
// B: 16-step key GRU scan on one 4-CTA cluster -> g_gates[16][256]
// C: 2048-step main GRU scan: 32 clusters x 4 CTAs, W_hh in SMEM,
//    h exchanged via DSMEM + barrier.cluster
// ---------------------------------------------------------------------------

#define T_STEPS 2048
#define BATCH   64
#define HID     256
#define ROWS_MAIN (T_STEPS * BATCH)
#define ROWS_ALL  (ROWS_MAIN + 64)
#define CSIZE 4
#define RPC   192          // weight rows per CTA (768/4)
#define WS    260          // padded k-stride (4t mod 32 -> conflict-free LDS.128)

__device__ float g_gi[(size_t)ROWS_ALL * 768];
__device__ float g_gates[16 * HID];

// ---------------- helpers ----------------
__device__ __forceinline__ uint32_t smem_u32(const void* p) {
    uint32_t a;
    asm("{ .reg .u64 t; cvta.to.shared.u64 t, %1; cvt.u32.u64 %0, t; }"
        : "=r"(a) : "l"(p));
    return a;
}
__device__ __forceinline__ void st_cluster_f32(uint32_t laddr, uint32_t rank, float v) {
    uint32_t ra;
    asm volatile("mapa.shared::cluster.u32 %0, %1, %2;" : "=r"(ra) : "r"(laddr), "r"(rank));
    asm volatile("st.shared::cluster.f32 [%0], %1;" :: "r"(ra), "f"(v) : "memory");
}
__device__ __forceinline__ void cluster_sync_() {
    asm volatile("barrier.cluster.arrive.aligned;" ::: "memory");
    asm volatile("barrier.cluster.wait.aligned;" ::: "memory");
}
__device__ __forceinline__ uint32_t ctarank() {
    uint32_t r; asm("mov.u32 %0, %%cluster_ctarank;" : "=r"(r)); return r;
}
__device__ __forceinline__ float sigmoidf_(float x) { return 1.0f / (1.0f + expf(-x)); }

// ---------------------------------------------------------------------------
// Kernel A: gi[row][n] = sum_k Arow[k] * wih[n][k] + bih[n]
// grid (12, 2049), block 256. Tile 64x64, K chunks of 32, 4x4 microtile.
// ---------------------------------------------------------------------------
__global__ void __launch_bounds__(256) kA(const float* __restrict__ x,
                                          const float* __restrict__ wmk,
                                          const float* __restrict__ wih,
                                          const float* __restrict__ bih)
{
    __shared__ __align__(16) float As[64][36];   // [m][kk]
    __shared__ __align__(16) float Bs[32][68];   // [kk][n]
    const int tid = threadIdx.x;
    const int nt = blockIdx.x;       // 0..11
    const int rt = blockIdx.y;       // 0..2048
    const int tx = tid & 15, ty = tid >> 4;
    const int m_base = rt * 64, n_base = nt * 64;

    float acc[4][4];
    #pragma unroll
    for (int i = 0; i < 4; ++i)
        #pragma unroll
        for (int j = 0; j < 4; ++j) acc[i][j] = 0.0f;

    for (int kc = 0; kc < 8; ++kc) {
        const int kb = kc * 32;
        __syncthreads();
        #pragma unroll
        for (int q = 0; q < 2; ++q) {
            int v  = tid + q * 256;
            int m  = v >> 3;
            int kk = (v & 7) << 2;
            // A tile
            int row = m_base + m;
            const float* asrc;
            if (row < ROWS_MAIN) {
                int t = row >> 6, b = row & 63;
                asrc = &x[((size_t)b * T_STEPS + t) * 256 + kb + kk];
            } else {
                int r2 = row - ROWS_MAIN;
                int l = r2 >> 2, kbk = r2 & 3;
                asrc = &wmk[((size_t)kbk * 16 + l) * 256 + kb + kk];
            }
            *(float4*)&As[m][kk] = *(const float4*)asrc;
            // B tile (transposed store)
            float4 g = *(const float4*)&wih[(size_t)(n_base + m) * 256 + kb + kk];
            Bs[kk + 0][m] = g.x; Bs[kk + 1][m] = g.y;
            Bs[kk + 2][m] = g.z; Bs[kk + 3][m] = g.w;
        }
        __syncthreads();
        #pragma unroll
        for (int k4 = 0; k4 < 32; k4 += 4) {
            float4 a0 = *(const float4*)&As[ty * 4 + 0][k4];
            float4 a1 = *(const float4*)&As[ty * 4 + 1][k4];
            float4 a2 = *(const float4*)&As[ty * 4 + 2][k4];
            float4 a3 = *(const float4*)&As[ty * 4 + 3][k4];
            float4 b0 = *(const float4*)&Bs[k4 + 0][tx * 4];
            float4 b1 = *(const float4*)&Bs[k4 + 1][tx * 4];
            float4 b2 = *(const float4*)&Bs[k4 + 2][tx * 4];
            float4 b3 = *(const float4*)&Bs[k4 + 3][tx * 4];
            float av[4][4] = {{a0.x,a0.y,a0.z,a0.w},{a1.x,a1.y,a1.z,a1.w},
                              {a2.x,a2.y,a2.z,a2.w},{a3.x,a3.y,a3.z,a3.w}};
            float bv[4][4] = {{b0.x,b0.y,b0.z,b0.w},{b1.x,b1.y,b1.z,b1.w},
                              {b2.x,b2.y,b2.z,b2.w},{b3.x,b3.y,b3.z,b3.w}};
            #pragma unroll
            for (int i = 0; i < 4; ++i)
                #pragma unroll
                for (int j = 0; j < 4; ++j) {
                    acc[i][j] += av[i][0] * bv[0][j];
                    acc[i][j] += av[i][1] * bv[1][j];
                    acc[i][j] += av[i][2] * bv[2][j];
                    acc[i][j] += av[i][3] * bv[3][j];
                }
        }
    }
    #pragma unroll
    for (int i = 0; i < 4; ++i) {
        size_t row = (size_t)(m_base + ty * 4 + i);
        #pragma unroll
        for (int j = 0; j < 4; ++j) {
            int n = n_base + tx * 4 + j;
            g_gi[row * 768 + n] = acc[i][j] + bih[n];
        }
    }
}

// ---------------------------------------------------------------------------
// Kernels B/C: GRU scan with cluster of 4 CTAs, W_hh slice in SMEM.
//   NB  = batch rows per cluster (4 for key scan, 2 for main scan)
//   KEY = key-gate scan (collect reset-gate means) vs main recurrence
// ---------------------------------------------------------------------------
template <int NB, bool KEY>
__global__ void __launch_bounds__(256, 1) __cluster_dims__(CSIZE, 1, 1)
gru_scan(const float* __restrict__ whh, const float* __restrict__ bhh,
         float* __restrict__ out)
{
    extern __shared__ __align__(16) float sm[];
    float* ws   = sm;                      // RPC*WS
    float* hsh  = ws + RPC * WS;           // NB*HID
    float* ghx  = hsh + NB * HID;          // 3*NB*64
    float* rbuf = ghx + 3 * NB * 64;       // NB*64 (KEY only)

    const int tid = threadIdx.x;
    const uint32_t rank = ctarank();
    const int cl = blockIdx.x / CSIZE;
    const int nsteps = KEY ? 16 : T_STEPS;

    // Load this CTA's weight slice (rows [rank*RPC, rank*RPC+RPC)) into SMEM
    for (int i = tid; i < RPC * 64; i += 256) {
        int r  = i >> 6;
        int k4 = (i & 63) << 2;
        *(float4*)&ws[r * WS + k4] =
            *(const float4*)&whh[((size_t)(rank * RPC + r)) * 256 + k4];
    }
    for (int i = tid; i < NB * HID; i += 256) hsh[i] = 0.0f;

    const uint32_t hsh_a = smem_u32(hsh);
    const uint32_t ghx_a = smem_u32(ghx);

    cluster_sync_();

    const int hl = tid & 63;
    const int bb = tid >> 6;
    const int hg = (int)rank * 64 + hl;   // this thread's owned hidden index

    for (int t = 0; t < nsteps; ++t) {
        // ---- prefetch gi (+ gate) for epilogue (covered by gh compute) ----
        float ir = 0.f, ii = 0.f, inn = 0.f, gg = 1.f;
        if (bb < NB) {
            size_t row = KEY ? (size_t)(ROWS_MAIN + t * 4 + bb)
                             : ((size_t)t * BATCH + (cl * NB + bb));
            const float* gp = &g_gi[row * 768];
            ir  = gp[hg];
            ii  = gp[256 + hg];
            inn = gp[512 + hg];
            if (!KEY && t < 16) gg = g_gates[t * 256 + hg];
        }

        // ---- gh = h @ W_hh^T + b_hh for owned rows ----
        if (tid < RPC) {
            const int rg = (int)rank * RPC + tid;   // global gate row 0..767
            float acc[NB];
            const float bv = bhh[rg];
            #pragma unroll
            for (int b = 0; b < NB; ++b) acc[b] = bv;
            const float* wr = &ws[tid * WS];
            #pragma unroll 4
            for (int k = 0; k < 256; k += 4) {
                float4 w = *(const float4*)&wr[k];
                #pragma unroll
                for (int b = 0; b < NB; ++b) {
                    float4 h4 = *(const float4*)&hsh[b * HID + k];
                    acc[b] += w.x * h4.x + w.y * h4.y + w.z * h4.z + w.w * h4.w;
                }
            }
            const int chunk = rg >> 8;          // 0=r,1=i,2=n
            const int hv    = rg & 255;
            const uint32_t owner = (uint32_t)(hv >> 6);
            const int hvl = hv & 63;
            #pragma unroll
            for (int b = 0; b < NB; ++b) {
                uint32_t addr = ghx_a + (uint32_t)(((chunk * NB + b) * 64 + hvl) * 4);
                st_cluster_f32(addr, owner, acc[b]);
            }
        }
        cluster_sync_();

        // ---- epilogue: owners combine gates, emit hy, broadcast new h ----
        if (bb < NB) {
            float hr = ghx[(0 * NB + bb) * 64 + hl];
            float hi = ghx[(1 * NB + bb) * 64 + hl];
            float hn = ghx[(2 * NB + bb) * 64 + hl];
            float r = sigmoidf_(ir + hr);
            float z = sigmoidf_(ii + hi);
            float n = tanhf(inn + r * hn);
            float hold = hsh[bb * HID + hg];
            float hy = n + z * (hold - n);
            if (KEY) {
                rbuf[bb * 64 + hl] = r;
            } else {
                out[((size_t)t * BATCH + (cl * NB + bb)) * HID + hg] = hy;
                hy *= gg;
            }
            uint32_t addr = hsh_a + (uint32_t)((bb * HID + hg) * 4);
            #pragma unroll
            for (uint32_t rk = 0; rk < CSIZE; ++rk)
                st_cluster_f32(addr, rk, hy);
        }
        if (KEY) {
            __syncthreads();
            if (tid < 64) {
                float s = 0.f;
                #pragma unroll
                for (int b = 0; b < NB; ++b) s += rbuf[b * 64 + tid];
                g_gates[t * 256 + (int)rank * 64 + tid] = s * (1.0f / NB);
            }
        }
        cluster_sync_();
    }
}

// ---------------------------------------------------------------------------
extern "C" void kernel_launch(void* const* d_in, const int* in_sizes, int n_in,
                              void* d_out, int out_size)
{
    const float* x   = (const float*)d_in[0];
    const float* wmk = (const float*)d_in[1];
    const float* wih = (const float*)d_in[2];
    const float* whh = (const float*)d_in[3];
    const float* bih = (const float*)d_in[4];
    const float* bhh = (const float*)d_in[5];
    float* out = (float*)d_out;

    constexpr int SMEM_KEY  = (RPC * WS + 4 * HID + 3 * 4 * 64 + 4 * 64) * 4;
    constexpr int SMEM_MAIN = (RPC * WS + 2 * HID + 3 * 2 * 64 + 2 * 64) * 4;

    cudaFuncSetAttribute((const void*)gru_scan<4, true>,
                         cudaFuncAttributeMaxDynamicSharedMemorySize, SMEM_KEY);
    cudaFuncSetAttribute((const void*)gru_scan<2, false>,
                         cudaFuncAttributeMaxDynamicSharedMemorySize, SMEM_MAIN);

    dim3 gA(12, 2049);
    kA<<<gA, 256>>>(x, wmk, wih, bih);
    gru_scan<4, true><<<CSIZE, 256, SMEM_KEY>>>(whh, bhh, out);
    gru_scan<2, false><<<32 * CSIZE, 256, SMEM_MAIN>>>(whh, bhh, out);
}

// round 3
// speedup vs baseline: 1.9067x; 1.9067x over previous
#include <cuda_runtime.h>
#include <cstdint>

// ---------------------------------------------------------------------------
// KeyedGRU  (B=64, T=2048, I=H=256, KB=4, KL=16)  -- all fp32
// A: gi = rows @ W_ih^T + b_ih for 131072 main rows + 64 key rows -> g_gi
//    128x128 tile, 8x8 microtile, fma.rn.f32x2 (FFMA2)
// B: 16-step key GRU scan, one 4-CTA cluster (row-partitioned, validated R1)
// C: 2048-step main GRU scan, 32 clusters x 4 CTAs, k-partitioned,
//    weights in REGISTERS, one barrier.cluster per step
// ---------------------------------------------------------------------------

#define T_STEPS 2048
#define BATCH   64
#define HID     256
#define ROWS_MAIN (T_STEPS * BATCH)
#define ROWS_ALL  (ROWS_MAIN + 64)
#define CSIZE 4
#define RPC   192
#define WS    260

__device__ float g_gi[(size_t)ROWS_ALL * 768];
__device__ float g_gates[16 * HID];

typedef unsigned long long ull;

// ---------------- helpers ----------------
__device__ __forceinline__ uint32_t smem_u32(const void* p) {
    uint32_t a;
    asm("{ .reg .u64 t; cvta.to.shared.u64 t, %1; cvt.u32.u64 %0, t; }"
        : "=r"(a) : "l"(p));
    return a;
}
__device__ __forceinline__ void st_cluster_f32(uint32_t laddr, uint32_t rank, float v) {
    uint32_t ra;
    asm volatile("mapa.shared::cluster.u32 %0, %1, %2;" : "=r"(ra) : "r"(laddr), "r"(rank));
    asm volatile("st.shared::cluster.f32 [%0], %1;" :: "r"(ra), "f"(v) : "memory");
}
__device__ __forceinline__ uint32_t mapa_addr(uint32_t laddr, uint32_t rank) {
    uint32_t ra;
    asm("mapa.shared::cluster.u32 %0, %1, %2;" : "=r"(ra) : "r"(laddr), "r"(rank));
    return ra;
}
__device__ __forceinline__ void st_cluster_2f(uint32_t ra, float a, float b) {
    asm volatile("{ .reg .b64 d; mov.b64 d, {%1,%2}; st.shared::cluster.b64 [%0], d; }"
                 :: "r"(ra), "f"(a), "f"(b) : "memory");
}
__device__ __forceinline__ void cluster_sync_() {
    asm volatile("barrier.cluster.arrive.aligned;" ::: "memory");
    asm volatile("barrier.cluster.wait.aligned;" ::: "memory");
}
__device__ __forceinline__ uint32_t ctarank() {
    uint32_t r; asm("mov.u32 %0, %%cluster_ctarank;" : "=r"(r)); return r;
}
__device__ __forceinline__ ull dup2(float a) {
    ull d; asm("mov.b64 %0, {%1, %1};" : "=l"(d) : "f"(a)); return d;
}
__device__ __forceinline__ void fma2(ull& c, ull a, ull b) {
    asm("fma.rn.f32x2 %0, %1, %2, %0;" : "+l"(c) : "l"(a), "l"(b));
}
__device__ __forceinline__ void unpk(ull v, float& x, float& y) {
    asm("mov.b64 {%0, %1}, %2;" : "=f"(x), "=f"(y) : "l"(v));
}
__device__ __forceinline__ float sigm_(float x) {
    return 1.0f / (1.0f + __expf(-x));
}
__device__ __forceinline__ float tanh_(float x) {
    return 1.0f - __fdividef(2.0f, __expf(2.0f * x) + 1.0f);
}
__device__ __forceinline__ float sigmoidf_(float x) { return 1.0f / (1.0f + expf(-x)); }

// ---------------------------------------------------------------------------
// Kernel A: 128x128 tile GEMM with FFMA2. grid (6, 1025), block 256.
// As[k][m] (m-contig), Bs[k][n] (n-contig), stride 132.
// Microtile: m = ty*8..+7 ; n = {tx*4..+3, 64+tx*4..+3}, acc as n-pairs.
// ---------------------------------------------------------------------------
__global__ void __launch_bounds__(256) kA(const float* __restrict__ x,
                                          const float* __restrict__ wmk,
                                          const float* __restrict__ wih,
                                          const float* __restrict__ bih)
{
    __shared__ __align__(16) float As[32][132];
    __shared__ __align__(16) float Bs[32][132];
    const int tid = threadIdx.x;
    const int nt = blockIdx.x;       // 0..5
    const int rt = blockIdx.y;       // 0..1024
    const int tx = tid & 15, ty = tid >> 4;
    const int m_base = rt * 128, n_base = nt * 128;

    ull acc[8][4];
    #pragma unroll
    for (int i = 0; i < 8; ++i)
        #pragma unroll
        for (int j = 0; j < 4; ++j) acc[i][j] = 0ull;

    // loader mapping: v = tid + q*256, m = v>>3, k4 = (v&7)<<2
    float4 ra[4], rb[4];

    auto load_regs = [&](int kc) {
        const int kb = kc * 32;
        #pragma unroll
        for (int q = 0; q < 4; ++q) {
            int v = tid + q * 256;
            int m = v >> 3;
            int k4 = (v & 7) << 2;
            int row = m_base + m;
            if (row < ROWS_MAIN) {
                int t = row >> 6, b = row & 63;
                ra[q] = *(const float4*)&x[((size_t)b * T_STEPS + t) * 256 + kb + k4];
            } else if (row < ROWS_ALL) {
                int r2 = row - ROWS_MAIN;
                int l = r2 >> 2, kbk = r2 & 3;
                ra[q] = *(const float4*)&wmk[((size_t)kbk * 16 + l) * 256 + kb + k4];
            } else {
                ra[q] = make_float4(0.f, 0.f, 0.f, 0.f);
            }
            rb[q] = *(const float4*)&wih[(size_t)(n_base + m) * 256 + kb + k4];
        }
    };

    load_regs(0);

    for (int kc = 0; kc < 8; ++kc) {
        __syncthreads();
        #pragma unroll
        for (int q = 0; q < 4; ++q) {
            int v = tid + q * 256;
            int m = v >> 3;
            int k4 = (v & 7) << 2;
            As[k4 + 0][m] = ra[q].x; As[k4 + 1][m] = ra[q].y;
            As[k4 + 2][m] = ra[q].z; As[k4 + 3][m] = ra[q].w;
            Bs[k4 + 0][m] = rb[q].x; Bs[k4 + 1][m] = rb[q].y;
            Bs[k4 + 2][m] = rb[q].z; Bs[k4 + 3][m] = rb[q].w;
        }
        __syncthreads();
        if (kc < 7) load_regs(kc + 1);

        #pragma unroll 8
        for (int k = 0; k < 32; ++k) {
            float4 a0 = *(const float4*)&As[k][ty * 8 + 0];
            float4 a1 = *(const float4*)&As[k][ty * 8 + 4];
            ulonglong2 b0 = *(const ulonglong2*)&Bs[k][tx * 4];
            ulonglong2 b1 = *(const ulonglong2*)&Bs[k][64 + tx * 4];
            ull ad[8];
            ad[0] = dup2(a0.x); ad[1] = dup2(a0.y); ad[2] = dup2(a0.z); ad[3] = dup2(a0.w);
            ad[4] = dup2(a1.x); ad[5] = dup2(a1.y); ad[6] = dup2(a1.z); ad[7] = dup2(a1.w);
            #pragma unroll
            for (int i = 0; i < 8; ++i) {
                fma2(acc[i][0], ad[i], b0.x);
                fma2(acc[i][1], ad[i], b0.y);
                fma2(acc[i][2], ad[i], b1.x);
                fma2(acc[i][3], ad[i], b1.y);
            }
        }
    }

    float4 bs0 = *(const float4*)&bih[n_base + tx * 4];
    float4 bs1 = *(const float4*)&bih[n_base + 64 + tx * 4];
    #pragma unroll
    for (int i = 0; i < 8; ++i) {
        int row = m_base + ty * 8 + i;
        if (row >= ROWS_ALL) break;
        float f0, f1, f2, f3;
        unpk(acc[i][0], f0, f1); unpk(acc[i][1], f2, f3);
        float4 o0 = make_float4(f0 + bs0.x, f1 + bs0.y, f2 + bs0.z, f3 + bs0.w);
        *(float4*)&g_gi[(size_t)row * 768 + n_base + tx * 4] = o0;
        unpk(acc[i][2], f0, f1); unpk(acc[i][3], f2, f3);
        float4 o1 = make_float4(f0 + bs1.x, f1 + bs1.y, f2 + bs1.z, f3 + bs1.w);
        *(float4*)&g_gi[(size_t)row * 768 + n_base + 64 + tx * 4] = o1;
    }
}

// ---------------------------------------------------------------------------
// Kernel B: key scan (16 steps, KB=4), row-partitioned, validated in R1.
// ---------------------------------------------------------------------------
__global__ void __launch_bounds__(256, 1) __cluster_dims__(CSIZE, 1, 1)
kB(const float* __restrict__ whh, const float* __restrict__ bhh)
{
    extern __shared__ __align__(16) float sm[];
    float* ws   = sm;                      // RPC*WS
    float* hsh  = ws + RPC * WS;           // 4*HID
    float* ghx  = hsh + 4 * HID;           // 3*4*64
    float* rbuf = ghx + 3 * 4 * 64;        // 4*64

    const int tid = threadIdx.x;
    const uint32_t rank = ctarank();

    for (int i = tid; i < RPC * 64; i += 256) {
        int r = i >> 6;
        int k4 = (i & 63) << 2;
        *(float4*)&ws[r * WS + k4] =
            *(const float4*)&whh[((size_t)(rank * RPC + r)) * 256 + k4];
    }
    for (int i = tid; i < 4 * HID; i += 256) hsh[i] = 0.0f;

    const uint32_t hsh_a = smem_u32(hsh);
    const uint32_t ghx_a = smem_u32(ghx);
    cluster_sync_();

    const int hl = tid & 63;
    const int bb = tid >> 6;
    const int hg = (int)rank * 64 + hl;

    for (int t = 0; t < 16; ++t) {
        float ir, ii, inn;
        {
            size_t row = (size_t)(ROWS_MAIN + t * 4 + bb);
            const float* gp = &g_gi[row * 768];
            ir = gp[hg]; ii = gp[256 + hg]; inn = gp[512 + hg];
        }
        if (tid < RPC) {
            const int rg = (int)rank * RPC + tid;
            float acc[4];
            const float bv = bhh[rg];
            #pragma unroll
            for (int b = 0; b < 4; ++b) acc[b] = bv;
            const float* wr = &ws[tid * WS];
            #pragma unroll 4
            for (int k = 0; k < 256; k += 4) {
                float4 w = *(const float4*)&wr[k];
                #pragma unroll
                for (int b = 0; b < 4; ++b) {
                    float4 h4 = *(const float4*)&hsh[b * HID + k];
                    acc[b] += w.x * h4.x + w.y * h4.y + w.z * h4.z + w.w * h4.w;
                }
            }
            const int chunk = rg >> 8;
            const int hv = rg & 255;
            const uint32_t owner = (uint32_t)(hv >> 6);
            const int hvl = hv & 63;
            #pragma unroll
            for (int b = 0; b < 4; ++b) {
                uint32_t addr = ghx_a + (uint32_t)(((chunk * 4 + b) * 64 + hvl) * 4);
                st_cluster_f32(addr, owner, acc[b]);
            }
        }
        cluster_sync_();
        {
            float hr = ghx[(0 * 4 + bb) * 64 + hl];
            float hi = ghx[(1 * 4 + bb) * 64 + hl];
            float hn = ghx[(2 * 4 + bb) * 64 + hl];
            float r = sigmoidf_(ir + hr);
            float z = sigmoidf_(ii + hi);
            float n = tanhf(inn + r * hn);
            float hold = hsh[bb * HID + hg];
            float hy = n + z * (hold - n);
            rbuf[bb * 64 + hl] = r;
            uint32_t addr = hsh_a + (uint32_t)((bb * HID + hg) * 4);
            #pragma unroll
            for (uint32_t rk = 0; rk < CSIZE; ++rk)
                st_cluster_f32(addr, rk, hy);
        }
        __syncthreads();
        if (tid < 64) {
            float s = 0.f;
            #pragma unroll
            for (int b = 0; b < 4; ++b) s += rbuf[b * 64 + tid];
            g_gates[t * 256 + (int)rank * 64 + tid] = s * 0.25f;
        }
        cluster_sync_();
    }
}

// ---------------------------------------------------------------------------
// Kernel C: main scan, k-partitioned, weights in registers, 1 sync/step.
// grid 128 (32 clusters x 4), block 256.
// CTA rank r owns k/h slice [r*64, r*64+64). Thread tid owns gate rows
// {tid, 256+tid, 512+tid} restricted to its k-slice: 3 x 64 weights in regs.
// acc paired over k (even,odd) via FFMA2. Partials shipped to h-owner CTA.
// ---------------------------------------------------------------------------
__global__ void __launch_bounds__(256, 1) __cluster_dims__(CSIZE, 1, 1)
kC(const float* __restrict__ whh, const float* __restrict__ bhh,
   float* __restrict__ out)
{
    // part[parity][src][gate][hl][b]  + h pairs
    __shared__ __align__(16) float part[2][4][3][64][2];   // 12 KB
    __shared__ __align__(16) float hp[2][64];              // [b][kk] local slice

    const int tid = threadIdx.x;
    const uint32_t rank = ctarank();
    const int cl = blockIdx.x >> 2;

    // ---- load weights into registers: wp[j][kpair] ----
    ull wp[3][32];
    {
        const float* wb = whh + (size_t)rank * 64;
        #pragma unroll
        for (int j = 0; j < 3; ++j) {
            const float* wr = wb + (size_t)(j * 256 + tid) * 256;
            #pragma unroll
            for (int kk = 0; kk < 64; kk += 4) {
                ulonglong2 v = *(const ulonglong2*)&wr[kk];
                wp[j][kk / 2] = v.x;
                wp[j][kk / 2 + 1] = v.y;
            }
        }
    }

    // init h slice
    if (tid < 128) hp[tid >> 6][tid & 63] = 0.0f;

    // destination for partials: owner of h-index (tid&255)=tid
    const uint32_t owner = (uint32_t)(tid >> 6);
    const int hvl = tid & 63;
    const uint32_t part_a = smem_u32(&part[0][0][0][0][0]);
    // local offset of part[0][rank][0][hvl][0]
    const uint32_t loff = (uint32_t)((rank * 3 * 64 * 2 + hvl * 2) * 4);
    const uint32_t ra_base = mapa_addr(part_a + loff, owner);

    // epilogue constants (tid < 128): b = tid>>6, hl = tid&63
    const int e_b = tid >> 6;
    const int e_hl = tid & 63;
    const int e_hg = (int)rank * 64 + e_hl;
    float bh_r = 0.f, bh_i = 0.f, bh_n = 0.f;
    if (tid < 128) {
        bh_r = bhh[e_hg];
        bh_i = bhh[256 + e_hg];
        bh_n = bhh[512 + e_hg];
    }
    const int b_glob = cl * 2 + e_b;

    cluster_sync_();

    for (int t = 0; t < T_STEPS; ++t) {
        // ---- prefetch gi + gate (covered by compute) ----
        float ir = 0.f, ii = 0.f, inn = 0.f, gg = 1.f;
        if (tid < 128) {
            const float* gp = &g_gi[((size_t)t * BATCH + b_glob) * 768];
            ir  = gp[e_hg];
            ii  = gp[256 + e_hg];
            inn = gp[512 + e_hg];
            if (t < 16) gg = g_gates[t * 256 + e_hg];
        }

        // ---- partial gh over local k-slice ----
        ull a00 = 0, a01 = 0, a10 = 0, a11 = 0, a20 = 0, a21 = 0;
        #pragma unroll
        for (int kk = 0; kk < 64; kk += 4) {
            ulonglong2 h0 = *(const ulonglong2*)&hp[0][kk];
            ulonglong2 h1 = *(const ulonglong2*)&hp[1][kk];
            ull w0a = wp[0][kk / 2], w0b = wp[0][kk / 2 + 1];
            ull w1a = wp[1][kk / 2], w1b = wp[1][kk / 2 + 1];
            ull w2a = wp[2][kk / 2], w2b = wp[2][kk / 2 + 1];
            fma2(a00, w0a, h0.x); fma2(a00, w0b, h0.y);
            fma2(a01, w0a, h1.x); fma2(a01, w0b, h1.y);
            fma2(a10, w1a, h0.x); fma2(a10, w1b, h0.y);
            fma2(a11, w1a, h1.x); fma2(a11, w1b, h1.y);
            fma2(a20, w2a, h0.x); fma2(a20, w2b, h0.y);
            fma2(a21, w2a, h1.x); fma2(a21, w2b, h1.y);
        }
        // reduce pairs and ship to owner
        {
            const uint32_t pbase = ra_base + (uint32_t)((t & 1) * 6144);
            float x0, y0, x1, y1;
            unpk(a00, x0, y0); unpk(a01, x1, y1);
            st_cluster_2f(pbase + 0 * 512, x0 + y0, x1 + y1);
            unpk(a10, x0, y0); unpk(a11, x1, y1);
            st_cluster_2f(pbase + 1 * 512, x0 + y0, x1 + y1);
            unpk(a20, x0, y0); unpk(a21, x1, y1);
            st_cluster_2f(pbase + 2 * 512, x0 + y0, x1 + y1);
        }
        cluster_sync_();

        // ---- epilogue: owner combines 4 partials, GRU cell, local h update --
        if (tid < 128) {
            const int p = t & 1;
            float s_r = bh_r, s_i = bh_i, s_n = bh_n;
            #pragma unroll
            for (int src = 0; src < 4; ++src) {
                s_r += part[p][src][0][e_hl][e_b];
                s_i += part[p][src][1][e_hl][e_b];
                s_n += part[p][src][2][e_hl][e_b];
            }
            float r = sigm_(ir + s_r);
            float z = sigm_(ii + s_i);
            float n = tanh_(inn + r * s_n);
            float hold = hp[e_b][e_hl];
            float hy = n + z * (hold - n);
            out[((size_t)t * BATCH + b_glob) * HID + e_hg] = hy;
            hp[e_b][e_hl] = hy * gg;
        }
        __syncthreads();
    }
}

// ---------------------------------------------------------------------------
extern "C" void kernel_launch(void* const* d_in, const int* in_sizes, int n_in,
                              void* d_out, int out_size)
{
    const float* x   = (const float*)d_in[0];
    const float* wmk = (const float*)d_in[1];
    const float* wih = (const float*)d_in[2];
    const float* whh = (const float*)d_in[3];
    const float* bih = (const float*)d_in[4];
    const float* bhh = (const float*)d_in[5];
    float* out = (float*)d_out;

    constexpr int SMEM_KEY = (RPC * WS + 4 * HID + 3 * 4 * 64 + 4 * 64) * 4;
    cudaFuncSetAttribute((const void*)kB,
                         cudaFuncAttributeMaxDynamicSharedMemorySize, SMEM_KEY);

    dim3 gA(6, 1025);
    kA<<<gA, 256>>>(x, wmk, wih, bih);
    kB<<<CSIZE, 256, SMEM_KEY>>>(whh, bhh);
    kC<<<32 * CSIZE, 256>>>(whh, bhh, out);
}